// round 7
// baseline (speedup 1.0000x reference)
#include <cuda_runtime.h>
#include <math.h>

#define UNITS 1536
#define NZ 6144                 // 4*UNITS
#define TPB 256                 // 256 thr * 4 cols = 1024 cols per block
#define XT 6                    // 6 column tiles * 1024 = 6144
#define CHAR_LEN 256
#define VOCAB 80
#define N_MIX 10
#define KA1 (3 + VOCAB)         // 83
#define KX  (3 + VOCAB + UNITS) // 1619
#define NS_X 32                 // splits for KX-row matrices
#define L_X 51                  // rows per split (32*51=1632 >= 1619)
#define NS_U 30                 // splits for U matrices
#define L_U 52                  // rows per split (30*52=1560 >= 1536)
#define W_X (XT * NS_X)         // 192 worker blocks per KX slab
#define W_U (XT * NS_U)         // 180 worker blocks per U slab

// ---------------- device scratch (no allocations allowed) ----------------
__device__ float g_part1[NS_X * NZ];    // chain partials (W1+U1, W2, W3)
__device__ float g_part2[NS_U * NZ];    // U2 @ h2
__device__ float g_part3[NS_U * NZ];    // U3 @ h3
__device__ float g_coefpart[48][30];
__device__ float g_x2[KX];              // [inputs, w, h1n]
__device__ float g_x3[KX];              // [inputs, w, h2n]
__device__ int g_cA, g_cB, g_cC, g_cD, g_cE, g_cF;

__device__ __forceinline__ float sigf(float x) { return 1.0f / (1.0f + expf(-x)); }

// ---------------- long-split GEMV worker, single segment --------------------
// Block owns 1024 cols (thread: one float4) and [k0, k0+len) rows; loops over
// 8-deep independent LDG.128 batches. Register-resident accumulation: ONE
// partial write at the end.
__device__ __forceinline__ void gemv_1seg(
    const float* __restrict__ M, const float* __restrict__ x,
    int Ktot, int k0, int len, int xt, int sout, float* __restrict__ part)
{
    int col4 = (xt * TPB + threadIdx.x) * 4;
    const float* Mc = M + col4 + (size_t)k0 * NZ;
    if (k0 + len > Ktot) len = Ktot - k0;

    float4 acc = make_float4(0.f, 0.f, 0.f, 0.f);
    int k = 0;
    for (; k + 8 <= len; k += 8) {
        float xv[8]; float4 r[8];
        #pragma unroll
        for (int i = 0; i < 8; ++i) {
            xv[i] = __ldg(x + k0 + k + i);
            r[i]  = *reinterpret_cast<const float4*>(Mc + (size_t)(k + i) * NZ);
        }
        #pragma unroll
        for (int i = 0; i < 8; ++i) {
            acc.x += xv[i] * r[i].x; acc.y += xv[i] * r[i].y;
            acc.z += xv[i] * r[i].z; acc.w += xv[i] * r[i].w;
        }
    }
    for (; k < len; ++k) {
        float xv = __ldg(x + k0 + k);
        float4 r = *reinterpret_cast<const float4*>(Mc + (size_t)k * NZ);
        acc.x += xv * r.x; acc.y += xv * r.y; acc.z += xv * r.z; acc.w += xv * r.w;
    }
    *reinterpret_cast<float4*>(part + (size_t)sout * NZ + col4) = acc;
}

// ---------------- long-split GEMV worker, three stacked segments ------------
// Rows [0,3)=inputs@W1, [3,83)=w_prev@W1, [83,1619)=h1@U1 (U1 separate ptr).
__device__ __forceinline__ void gemv_3seg(
    const float* __restrict__ W1, const float* __restrict__ inputs,
    const float* __restrict__ wprev,
    const float* __restrict__ U1, const float* __restrict__ h1,
    int k0, int len, int xt, int sout, float* __restrict__ part)
{
    int col4 = (xt * TPB + threadIdx.x) * 4;
    if (k0 + len > KX) len = KX - k0;

    float4 acc = make_float4(0.f, 0.f, 0.f, 0.f);
    int k = 0;
    for (; k + 8 <= len; k += 8) {
        float xv[8]; float4 r[8];
        #pragma unroll
        for (int i = 0; i < 8; ++i) {
            int kk = k0 + k + i;
            const float* rp; float xval;
            if (kk < 3)         { rp = W1 + (size_t)kk * NZ;         xval = __ldg(inputs + kk); }
            else if (kk < KA1)  { rp = W1 + (size_t)kk * NZ;         xval = __ldg(wprev + kk - 3); }
            else                { rp = U1 + (size_t)(kk - KA1) * NZ; xval = __ldg(h1 + kk - KA1); }
            xv[i] = xval;
            r[i] = *reinterpret_cast<const float4*>(rp + col4);
        }
        #pragma unroll
        for (int i = 0; i < 8; ++i) {
            acc.x += xv[i] * r[i].x; acc.y += xv[i] * r[i].y;
            acc.z += xv[i] * r[i].z; acc.w += xv[i] * r[i].w;
        }
    }
    for (; k < len; ++k) {
        int kk = k0 + k;
        const float* rp; float xval;
        if (kk < 3)         { rp = W1 + (size_t)kk * NZ;         xval = __ldg(inputs + kk); }
        else if (kk < KA1)  { rp = W1 + (size_t)kk * NZ;         xval = __ldg(wprev + kk - 3); }
        else                { rp = U1 + (size_t)(kk - KA1) * NZ; xval = __ldg(h1 + kk - KA1); }
        float4 r = *reinterpret_cast<const float4*>(rp + col4);
        acc.x += xval * r.x; acc.y += xval * r.y; acc.z += xval * r.z; acc.w += xval * r.w;
    }
    *reinterpret_cast<float4*>(part + (size_t)sout * NZ + col4) = acc;
}

// ---------------- gates: reduce partials + LSTM nonlinearity (256 thr) ------
__device__ __forceinline__ void gates_body(
    int blk, const float* __restrict__ b, const float* __restrict__ c_in,
    const float* __restrict__ pA, int nsA,
    const float* __restrict__ pB, int nsB,
    float* __restrict__ out_h, float* __restrict__ xnext,
    const float* __restrict__ Wd)
{
    __shared__ float red[8][32][4];
    __shared__ float hsh[32];
    __shared__ float csh[4][30];
    int t = threadIdx.x, ul = t & 31, sg = t >> 5;   // 8 subgroups
    int u = blk * 32 + ul;

    float s0 = 0.f, s1 = 0.f, s2 = 0.f, s3 = 0.f;
    for (int s = sg; s < nsA; s += 8) {
        const float* row = pA + (size_t)s * NZ;
        s0 += row[u]; s1 += row[u + UNITS]; s2 += row[u + 2 * UNITS]; s3 += row[u + 3 * UNITS];
    }
    for (int s = sg; s < nsB; s += 8) {
        const float* row = pB + (size_t)s * NZ;
        s0 += row[u]; s1 += row[u + UNITS]; s2 += row[u + 2 * UNITS]; s3 += row[u + 3 * UNITS];
    }
    red[sg][ul][0] = s0; red[sg][ul][1] = s1; red[sg][ul][2] = s2; red[sg][ul][3] = s3;
    __syncthreads();

    if (sg == 0) {
        float zi = b[u], zf = b[u + UNITS], zg = b[u + 2 * UNITS], zo = b[u + 3 * UNITS];
        #pragma unroll
        for (int g = 0; g < 8; ++g) {
            zi += red[g][ul][0]; zf += red[g][ul][1];
            zg += red[g][ul][2]; zo += red[g][ul][3];
        }
        float c = sigf(zf) * c_in[u] + sigf(zi) * tanhf(zg);
        float h = sigf(zo) * tanhf(c);
        out_h[u] = h;
        if (xnext) xnext[u] = h;
        hsh[ul] = h;
    }

    if (Wd) {
        __syncthreads();
        if (t < 120) {                       // j = t%30, group g = t/30 (8 units each)
            int j = t % 30, g = t / 30;
            int ub = blk * 32 + g * 8;
            float s = 0.f;
            #pragma unroll
            for (int i = 0; i < 8; ++i)
                s += hsh[g * 8 + i] * __ldg(Wd + (size_t)(ub + i) * 30 + j);
            csh[g][j] = s;
        }
        __syncthreads();
        if (t < 30)
            g_coefpart[blk][t] = csh[0][t] + csh[1][t] + csh[2][t] + csh[3][t];
    }
}

// ---------------- window finisher (256 threads) ------------------------------
__device__ __forceinline__ void window_body(
    const float* __restrict__ bd, const float* __restrict__ kp,
    const float* __restrict__ sentence, const float* __restrict__ inputs)
{
    __shared__ float coef[30];
    __shared__ float alpha[N_MIX], beta[N_MIX], kap[N_MIX];
    __shared__ float phi[CHAR_LEN];
    __shared__ float wpart[8][VOCAB];
    int t = threadIdx.x, warp = t >> 5, lane = t & 31;

    if (t < 3) { g_x2[t] = inputs[t]; g_x3[t] = inputs[t]; }
    if (t < 30) {
        float s = bd[t];
        #pragma unroll
        for (int blk = 0; blk < 48; ++blk) s += g_coefpart[blk][t];
        coef[t] = s;
    }
    __syncthreads();
    if (t < N_MIX) {
        alpha[t] = expf(coef[t]);
        beta[t]  = expf(coef[N_MIX + t]);
        kap[t]   = kp[t] + expf(coef[2 * N_MIX + t]);
    }
    __syncthreads();
    {
        float u = (float)(t + 1);
        float p = 0.f;
        #pragma unroll
        for (int m = 0; m < N_MIX; ++m) {
            float d = kap[m] - u;
            p += alpha[m] * expf(-beta[m] * d * d);
        }
        phi[t] = p;                           // t covers 0..255 exactly
    }
    __syncthreads();
    {
        float a0 = 0.f, a1 = 0.f, a2 = 0.f;
        #pragma unroll 8
        for (int cc = 0; cc < 32; ++cc) {
            int c = warp * 32 + cc;
            float pv = phi[c];
            const float* row = sentence + (size_t)c * VOCAB;
            a0 += pv * __ldg(row + lane);
            a1 += pv * __ldg(row + 32 + lane);
            if (lane < 16) a2 += pv * __ldg(row + 64 + lane);
        }
        wpart[warp][lane]      = a0;
        wpart[warp][lane + 32] = a1;
        if (lane < 16) wpart[warp][lane + 64] = a2;
    }
    __syncthreads();
    if (t < VOCAB) {
        float s = 0.f;
        #pragma unroll
        for (int w = 0; w < 8; ++w) s += wpart[w][t];
        g_x2[3 + t] = s;
        g_x3[3 + t] = s;
    }
}

// ---------------- launch A: mega GEMV + gates1 + coef + window --------------
// bids: [0,192) W1+U1 -> part1 ; [192,372) U2 -> part2 ; [372,552) U3 -> part3
//       [552,600) gates1 ; 600 window
__global__ void __launch_bounds__(TPB) fusedA(
    const float* __restrict__ W1, const float* __restrict__ inputs,
    const float* __restrict__ wprev, const float* __restrict__ U1, const float* __restrict__ h1,
    const float* __restrict__ U2, const float* __restrict__ h2,
    const float* __restrict__ U3, const float* __restrict__ h3,
    const float* __restrict__ b1, const float* __restrict__ c1, float* __restrict__ out,
    const float* __restrict__ Wd, const float* __restrict__ bd,
    const float* __restrict__ kappa_prev, const float* __restrict__ sentence)
{
    int bid = blockIdx.x;
    if (bid < W_X) {
        int split = bid / XT, xt = bid % XT;
        gemv_3seg(W1, inputs, wprev, U1, h1, split * L_X, L_X, xt, split, g_part1);
        __syncthreads();
        if (threadIdx.x == 0) { __threadfence(); atomicAdd(&g_cA, 1); }
    } else if (bid < W_X + W_U) {
        int r = bid - W_X, split = r / XT, xt = r % XT;
        gemv_1seg(U2, h2, UNITS, split * L_U, L_U, xt, split, g_part2);
    } else if (bid < W_X + 2 * W_U) {
        int r = bid - W_X - W_U, split = r / XT, xt = r % XT;
        gemv_1seg(U3, h3, UNITS, split * L_U, L_U, xt, split, g_part3);
    } else if (bid < W_X + 2 * W_U + 48) {
        int blk = bid - W_X - 2 * W_U;
        if (threadIdx.x == 0) { while (((volatile int*)&g_cA)[0] < W_X) __nanosleep(32); }
        __syncthreads(); __threadfence();
        gates_body(blk, b1, c1, g_part1, NS_X, nullptr, 0, out, g_x2 + KA1, Wd);
        __syncthreads();
        if (threadIdx.x == 0) { __threadfence(); atomicAdd(&g_cB, 1); }
    } else {
        if (threadIdx.x == 0) { while (((volatile int*)&g_cB)[0] < 48) __nanosleep(32); }
        __syncthreads(); __threadfence();
        window_body(bd, kappa_prev, sentence, inputs);
        __syncthreads();
        if (threadIdx.x == 0) { g_cA = 0; g_cB = 0; __threadfence(); }
    }
}

// ---------------- launch B/C: chain GEMV + gates ----------------------------
__global__ void __launch_bounds__(TPB) fusedChain(
    const float* __restrict__ W, const float* __restrict__ x,
    const float* __restrict__ pB, int nsB,
    const float* __restrict__ b, const float* __restrict__ c_in,
    float* __restrict__ out_h, float* __restrict__ xnext,
    int* __restrict__ cW, int* __restrict__ cG)
{
    int bid = blockIdx.x;
    if (bid < W_X) {
        int split = bid / XT, xt = bid % XT;
        gemv_1seg(W, x, KX, split * L_X, L_X, xt, split, g_part1);
        __syncthreads();
        if (threadIdx.x == 0) { __threadfence(); atomicAdd(cW, 1); }
    } else {
        int blk = bid - W_X;
        if (threadIdx.x == 0) { while (((volatile int*)cW)[0] < W_X) __nanosleep(32); }
        __syncthreads(); __threadfence();
        gates_body(blk, b, c_in, g_part1, NS_X, pB, nsB, out_h, xnext, nullptr);
        __syncthreads();
        if (threadIdx.x == 0) {
            __threadfence();
            int v = atomicAdd(cG, 1);
            if (v == 47) { *cW = 0; *cG = 0; __threadfence(); }
        }
    }
}

// ---------------- launch ----------------
extern "C" void kernel_launch(void* const* d_in, const int* in_sizes, int n_in,
                              void* d_out, int out_size)
{
    const float* inputs     = (const float*)d_in[0];
    const float* h1_in      = (const float*)d_in[1];
    const float* c1_in      = (const float*)d_in[2];
    const float* h2_in      = (const float*)d_in[3];
    const float* c2_in      = (const float*)d_in[4];
    const float* h3_in      = (const float*)d_in[5];
    const float* c3_in      = (const float*)d_in[6];
    const float* w_prev     = (const float*)d_in[7];
    const float* kappa_prev = (const float*)d_in[8];
    const float* sentence   = (const float*)d_in[9];
    const float* W1 = (const float*)d_in[10];
    const float* U1 = (const float*)d_in[11];
    const float* b1 = (const float*)d_in[12];
    const float* Wd = (const float*)d_in[13];
    const float* bd = (const float*)d_in[14];
    const float* W2 = (const float*)d_in[15];
    const float* U2 = (const float*)d_in[16];
    const float* b2 = (const float*)d_in[17];
    const float* W3 = (const float*)d_in[18];
    const float* U3 = (const float*)d_in[19];
    const float* b3 = (const float*)d_in[20];
    float* out = (float*)d_out;

    float *x2p, *x3p, *p2p, *p3p;
    cudaGetSymbolAddress((void**)&x2p, g_x2);
    cudaGetSymbolAddress((void**)&x3p, g_x3);
    cudaGetSymbolAddress((void**)&p2p, g_part2);
    cudaGetSymbolAddress((void**)&p3p, g_part3);
    int *cCp, *cDp, *cEp, *cFp;
    cudaGetSymbolAddress((void**)&cCp, g_cC);
    cudaGetSymbolAddress((void**)&cDp, g_cD);
    cudaGetSymbolAddress((void**)&cEp, g_cE);
    cudaGetSymbolAddress((void**)&cFp, g_cF);

    // A: mega GEMV (W1+U1, U2@h2, U3@h3) + gates1 + coef + window
    fusedA<<<W_X + 2 * W_U + 49, TPB>>>(W1, inputs, w_prev, U1, h1_in,
                                        U2, h2_in, U3, h3_in,
                                        b1, c1_in, out, Wd, bd, kappa_prev, sentence);

    // B: W2 @ x2 -> part1 ; gates2 reduces part1 + part2
    fusedChain<<<W_X + 48, TPB>>>(W2, x2p, p2p, NS_U, b2, c2_in,
                                  out + UNITS, x3p + KA1, cCp, cDp);

    // C: W3 @ x3 -> part1 ; gates3 reduces part1 + part3
    fusedChain<<<W_X + 48, TPB>>>(W3, x3p, p3p, NS_U, b3, c3_in,
                                  out + 2 * UNITS, nullptr, cEp, cFp);
}

// round 9
// speedup vs baseline: 1.2122x; 1.2122x over previous
#include <cuda_runtime.h>
#include <math.h>
#include <stdint.h>

#define UNITS 1536
#define NZ 6144                 // 4*UNITS
#define TPB 256                 // 256 thr * 4 cols = 1024 cols per block
#define XT 6                    // 6 column tiles * 1024 = 6144
#define DEPTH 8                 // cp.async pipeline depth (row groups)
#define CHAR_LEN 256
#define VOCAB 80
#define N_MIX 10
#define KA1 (3 + VOCAB)         // 83
#define KX  (3 + VOCAB + UNITS) // 1619
#define NS 48                   // splits per matrix
#define L_X 34                  // rows per split, KX matrices (48*34=1632)
#define L_U 32                  // rows per split, U matrices (48*32=1536)
#define W_W (XT * NS)           // 288 worker blocks per matrix slab

// ---------------- device scratch (no allocations allowed) ----------------
__device__ float g_part1[NS * NZ];      // chain partials (W1+U1, W2, W3)
__device__ float g_part2[NS * NZ];      // U2 @ h2
__device__ float g_part3[NS * NZ];      // U3 @ h3
__device__ float g_coefpart[48][30];
__device__ float g_x2[KX];              // [inputs, w, h1n]
__device__ float g_x3[KX];              // [inputs, w, h2n]
__device__ int g_cA, g_cB, g_cC, g_cD, g_cE, g_cF;

__device__ __forceinline__ float sigf(float x) { return 1.0f / (1.0f + expf(-x)); }

__device__ __forceinline__ void cp16(unsigned sdst, const float* gsrc) {
    asm volatile("cp.async.cg.shared.global [%0], [%1], 16;" :: "r"(sdst), "l"(gsrc));
}
__device__ __forceinline__ void cp_commit() {
    asm volatile("cp.async.commit_group;" ::: "memory");
}
template<int N> __device__ __forceinline__ void cp_wait() {
    asm volatile("cp.async.wait_group %0;" :: "n"(N) : "memory");
}

// ---------------- async-pipelined GEMV worker -------------------------------
// Block owns 1024 cols; streams [k0, k0+len) rows through an 8-slot smem ring.
// Each thread owns one 16B lane of each slot -> no intra-loop barriers.
struct Smem {
    float4 buf[DEPTH][TPB];
    float xs[64];
};

template<bool SEG3>
__device__ __forceinline__ void gemv_async(
    Smem* sm,
    const float* __restrict__ W1, const float* __restrict__ U1,
    const float* __restrict__ inputs, const float* __restrict__ wprev,
    const float* __restrict__ h1,
    const float* __restrict__ M, const float* __restrict__ x,
    int Ktot, int k0, int len, int xt, int sout, float* __restrict__ part)
{
    int t = threadIdx.x;
    int col4 = (xt * TPB + t) * 4;
    if (k0 + len > Ktot) len = Ktot - k0;

    // stage x values (one barrier, outside pipeline)
    if (t < len) {
        int kk = k0 + t;
        float xv;
        if (SEG3) {
            if (kk < 3)        xv = __ldg(inputs + kk);
            else if (kk < KA1) xv = __ldg(wprev + kk - 3);
            else               xv = __ldg(h1 + kk - KA1);
        } else {
            xv = __ldg(x + kk);
        }
        sm->xs[t] = xv;
    }
    __syncthreads();

    // prologue: fill pipeline
    int npro = (len < DEPTH) ? len : DEPTH;
    for (int i = 0; i < npro; ++i) {
        int kk = k0 + i;
        const float* rp = SEG3
            ? ((kk < KA1) ? (W1 + (size_t)kk * NZ) : (U1 + (size_t)(kk - KA1) * NZ))
            : (M + (size_t)kk * NZ);
        cp16((unsigned)__cvta_generic_to_shared(&sm->buf[i][t]), rp + col4);
        cp_commit();
    }

    float4 acc = make_float4(0.f, 0.f, 0.f, 0.f);
    for (int r = 0; r < len; ++r) {
        if (r + DEPTH <= len) cp_wait<DEPTH - 1>();
        else if (r + DEPTH == len + 1 || (r == 0 && len < DEPTH)) cp_wait<0>();
        float4 v = sm->buf[r & (DEPTH - 1)][t];
        float xv = sm->xs[r];
        acc.x += xv * v.x; acc.y += xv * v.y; acc.z += xv * v.z; acc.w += xv * v.w;
        int nr = r + DEPTH;
        if (nr < len) {
            int kk = k0 + nr;
            const float* rp = SEG3
                ? ((kk < KA1) ? (W1 + (size_t)kk * NZ) : (U1 + (size_t)(kk - KA1) * NZ))
                : (M + (size_t)kk * NZ);
            cp16((unsigned)__cvta_generic_to_shared(&sm->buf[nr & (DEPTH - 1)][t]), rp + col4);
            cp_commit();
        }
    }
    *reinterpret_cast<float4*>(part + (size_t)sout * NZ + col4) = acc;
}

// ---------------- gates: reduce partials + LSTM nonlinearity (256 thr) ------
__device__ __forceinline__ void gates_body(
    int blk, const float* __restrict__ b, const float* __restrict__ c_in,
    const float* __restrict__ pA, int nsA,
    const float* __restrict__ pB, int nsB,
    float* __restrict__ out_h, float* __restrict__ xnext,
    const float* __restrict__ Wd)
{
    __shared__ float red[8][32][4];
    __shared__ float hsh[32];
    __shared__ float csh[4][30];
    int t = threadIdx.x, ul = t & 31, sg = t >> 5;   // 8 subgroups
    int u = blk * 32 + ul;

    float s0 = 0.f, s1 = 0.f, s2 = 0.f, s3 = 0.f;
    for (int s = sg; s < nsA; s += 8) {
        const float* row = pA + (size_t)s * NZ;
        s0 += row[u]; s1 += row[u + UNITS]; s2 += row[u + 2 * UNITS]; s3 += row[u + 3 * UNITS];
    }
    for (int s = sg; s < nsB; s += 8) {
        const float* row = pB + (size_t)s * NZ;
        s0 += row[u]; s1 += row[u + UNITS]; s2 += row[u + 2 * UNITS]; s3 += row[u + 3 * UNITS];
    }
    red[sg][ul][0] = s0; red[sg][ul][1] = s1; red[sg][ul][2] = s2; red[sg][ul][3] = s3;
    __syncthreads();

    if (sg == 0) {
        float zi = b[u], zf = b[u + UNITS], zg = b[u + 2 * UNITS], zo = b[u + 3 * UNITS];
        #pragma unroll
        for (int g = 0; g < 8; ++g) {
            zi += red[g][ul][0]; zf += red[g][ul][1];
            zg += red[g][ul][2]; zo += red[g][ul][3];
        }
        float c = sigf(zf) * c_in[u] + sigf(zi) * tanhf(zg);
        float h = sigf(zo) * tanhf(c);
        out_h[u] = h;
        if (xnext) xnext[u] = h;
        hsh[ul] = h;
    }

    if (Wd) {
        __syncthreads();
        if (t < 120) {                       // j = t%30, group g = t/30 (8 units each)
            int j = t % 30, g = t / 30;
            int ub = blk * 32 + g * 8;
            float s = 0.f;
            #pragma unroll
            for (int i = 0; i < 8; ++i)
                s += hsh[g * 8 + i] * __ldg(Wd + (size_t)(ub + i) * 30 + j);
            csh[g][j] = s;
        }
        __syncthreads();
        if (t < 30)
            g_coefpart[blk][t] = csh[0][t] + csh[1][t] + csh[2][t] + csh[3][t];
    }
}

// ---------------- window finisher (256 threads) ------------------------------
__device__ __forceinline__ void window_body(
    const float* __restrict__ bd, const float* __restrict__ kp,
    const float* __restrict__ sentence, const float* __restrict__ inputs)
{
    __shared__ float coef[30];
    __shared__ float alpha[N_MIX], beta[N_MIX], kap[N_MIX];
    __shared__ float phi[CHAR_LEN];
    __shared__ float wpart[8][VOCAB];
    int t = threadIdx.x, warp = t >> 5, lane = t & 31;

    if (t < 3) { g_x2[t] = inputs[t]; g_x3[t] = inputs[t]; }
    if (t < 30) {
        float s = bd[t];
        #pragma unroll
        for (int blk = 0; blk < 48; ++blk) s += g_coefpart[blk][t];
        coef[t] = s;
    }
    __syncthreads();
    if (t < N_MIX) {
        alpha[t] = expf(coef[t]);
        beta[t]  = expf(coef[N_MIX + t]);
        kap[t]   = kp[t] + expf(coef[2 * N_MIX + t]);
    }
    __syncthreads();
    {
        float u = (float)(t + 1);
        float p = 0.f;
        #pragma unroll
        for (int m = 0; m < N_MIX; ++m) {
            float d = kap[m] - u;
            p += alpha[m] * expf(-beta[m] * d * d);
        }
        phi[t] = p;                           // t covers 0..255 exactly
    }
    __syncthreads();
    {
        float a0 = 0.f, a1 = 0.f, a2 = 0.f;
        #pragma unroll 8
        for (int cc = 0; cc < 32; ++cc) {
            int c = warp * 32 + cc;
            float pv = phi[c];
            const float* row = sentence + (size_t)c * VOCAB;
            a0 += pv * __ldg(row + lane);
            a1 += pv * __ldg(row + 32 + lane);
            if (lane < 16) a2 += pv * __ldg(row + 64 + lane);
        }
        wpart[warp][lane]      = a0;
        wpart[warp][lane + 32] = a1;
        if (lane < 16) wpart[warp][lane + 64] = a2;
    }
    __syncthreads();
    if (t < VOCAB) {
        float s = 0.f;
        #pragma unroll
        for (int w = 0; w < 8; ++w) s += wpart[w][t];
        g_x2[3 + t] = s;
        g_x3[3 + t] = s;
    }
}

// ---------------- launch A: mega GEMV + gates1 + coef + window --------------
// bids: [0,288) W1+U1 -> part1 ; [288,576) U2 -> part2 ; [576,864) U3 -> part3
//       [864,912) gates1 ; 912 window
__global__ void __launch_bounds__(TPB) fusedA(
    const float* __restrict__ W1, const float* __restrict__ inputs,
    const float* __restrict__ wprev, const float* __restrict__ U1, const float* __restrict__ h1,
    const float* __restrict__ U2, const float* __restrict__ h2,
    const float* __restrict__ U3, const float* __restrict__ h3,
    const float* __restrict__ b1, const float* __restrict__ c1, float* __restrict__ out,
    const float* __restrict__ Wd, const float* __restrict__ bd,
    const float* __restrict__ kappa_prev, const float* __restrict__ sentence)
{
    __shared__ Smem sm;
    int bid = blockIdx.x;
    if (bid < W_W) {
        int split = bid / XT, xt = bid % XT;
        gemv_async<true>(&sm, W1, U1, inputs, wprev, h1, nullptr, nullptr,
                         KX, split * L_X, L_X, xt, split, g_part1);
        __syncthreads();
        if (threadIdx.x == 0) { __threadfence(); atomicAdd(&g_cA, 1); }
    } else if (bid < 2 * W_W) {
        int r = bid - W_W, split = r / XT, xt = r % XT;
        gemv_async<false>(&sm, nullptr, nullptr, nullptr, nullptr, nullptr, U2, h2,
                          UNITS, split * L_U, L_U, xt, split, g_part2);
    } else if (bid < 3 * W_W) {
        int r = bid - 2 * W_W, split = r / XT, xt = r % XT;
        gemv_async<false>(&sm, nullptr, nullptr, nullptr, nullptr, nullptr, U3, h3,
                          UNITS, split * L_U, L_U, xt, split, g_part3);
    } else if (bid < 3 * W_W + 48) {
        int blk = bid - 3 * W_W;
        if (threadIdx.x == 0) { while (((volatile int*)&g_cA)[0] < W_W) __nanosleep(32); }
        __syncthreads(); __threadfence();
        gates_body(blk, b1, c1, g_part1, NS, nullptr, 0, out, g_x2 + KA1, Wd);
        __syncthreads();
        if (threadIdx.x == 0) { __threadfence(); atomicAdd(&g_cB, 1); }
    } else {
        if (threadIdx.x == 0) { while (((volatile int*)&g_cB)[0] < 48) __nanosleep(32); }
        __syncthreads(); __threadfence();
        window_body(bd, kappa_prev, sentence, inputs);
        __syncthreads();
        if (threadIdx.x == 0) { g_cA = 0; g_cB = 0; __threadfence(); }
    }
}

// ---------------- launch B/C: chain GEMV + gates ----------------------------
__global__ void __launch_bounds__(TPB) fusedChain(
    const float* __restrict__ W, const float* __restrict__ x,
    const float* __restrict__ pB, int nsB,
    const float* __restrict__ b, const float* __restrict__ c_in,
    float* __restrict__ out_h, float* __restrict__ xnext,
    int* __restrict__ cW, int* __restrict__ cG)
{
    __shared__ Smem sm;
    int bid = blockIdx.x;
    if (bid < W_W) {
        int split = bid / XT, xt = bid % XT;
        gemv_async<false>(&sm, nullptr, nullptr, nullptr, nullptr, nullptr, W, x,
                          KX, split * L_X, L_X, xt, split, g_part1);
        __syncthreads();
        if (threadIdx.x == 0) { __threadfence(); atomicAdd(cW, 1); }
    } else {
        int blk = bid - W_W;
        if (threadIdx.x == 0) { while (((volatile int*)cW)[0] < W_W) __nanosleep(32); }
        __syncthreads(); __threadfence();
        gates_body(blk, b, c_in, g_part1, NS, pB, nsB, out_h, xnext, nullptr);
        __syncthreads();
        if (threadIdx.x == 0) {
            __threadfence();
            int v = atomicAdd(cG, 1);
            if (v == 47) { *cW = 0; *cG = 0; __threadfence(); }
        }
    }
}

// ---------------- launch ----------------
extern "C" void kernel_launch(void* const* d_in, const int* in_sizes, int n_in,
                              void* d_out, int out_size)
{
    const float* inputs     = (const float*)d_in[0];
    const float* h1_in      = (const float*)d_in[1];
    const float* c1_in      = (const float*)d_in[2];
    const float* h2_in      = (const float*)d_in[3];
    const float* c2_in      = (const float*)d_in[4];
    const float* h3_in      = (const float*)d_in[5];
    const float* c3_in      = (const float*)d_in[6];
    const float* w_prev     = (const float*)d_in[7];
    const float* kappa_prev = (const float*)d_in[8];
    const float* sentence   = (const float*)d_in[9];
    const float* W1 = (const float*)d_in[10];
    const float* U1 = (const float*)d_in[11];
    const float* b1 = (const float*)d_in[12];
    const float* Wd = (const float*)d_in[13];
    const float* bd = (const float*)d_in[14];
    const float* W2 = (const float*)d_in[15];
    const float* U2 = (const float*)d_in[16];
    const float* b2 = (const float*)d_in[17];
    const float* W3 = (const float*)d_in[18];
    const float* U3 = (const float*)d_in[19];
    const float* b3 = (const float*)d_in[20];
    float* out = (float*)d_out;

    float *x2p, *x3p, *p2p, *p3p;
    cudaGetSymbolAddress((void**)&x2p, g_x2);
    cudaGetSymbolAddress((void**)&x3p, g_x3);
    cudaGetSymbolAddress((void**)&p2p, g_part2);
    cudaGetSymbolAddress((void**)&p3p, g_part3);
    int *cCp, *cDp, *cEp, *cFp;
    cudaGetSymbolAddress((void**)&cCp, g_cC);
    cudaGetSymbolAddress((void**)&cDp, g_cD);
    cudaGetSymbolAddress((void**)&cEp, g_cE);
    cudaGetSymbolAddress((void**)&cFp, g_cF);

    // A: mega GEMV (W1+U1, U2@h2, U3@h3) + gates1 + coef + window
    fusedA<<<3 * W_W + 49, TPB>>>(W1, inputs, w_prev, U1, h1_in,
                                  U2, h2_in, U3, h3_in,
                                  b1, c1_in, out, Wd, bd, kappa_prev, sentence);

    // B: W2 @ x2 -> part1 ; gates2 reduces part1 + part2
    fusedChain<<<W_W + 48, TPB>>>(W2, x2p, p2p, NS, b2, c2_in,
                                  out + UNITS, x3p + KA1, cCp, cDp);

    // C: W3 @ x3 -> part1 ; gates3 reduces part1 + part3
    fusedChain<<<W_W + 48, TPB>>>(W3, x3p, p3p, NS, b3, c3_in,
                                  out + 2 * UNITS, nullptr, cEp, cFp);
}